// round 1
// baseline (speedup 1.0000x reference)
#include <cuda_runtime.h>
#include <math.h>

#define C_DIM 512
#define N_DIM 64
#define HW_DIM 1024
#define M_TOT (N_DIM * HW_DIM)   // 65536
#define EPS_V 1e-5f
#define T_ITERS 5

// ---------------- scratch (no allocation allowed) ----------------
__device__ float g_mean[C_DIM];
__device__ float g_bias[C_DIM];
__device__ float g_Gram[C_DIM * C_DIM];
__device__ float g_S[C_DIM * C_DIM];       // Sigma, then Sigma_N (in place scale)
__device__ float g_Pa[C_DIM * C_DIM];
__device__ float g_Pb[C_DIM * C_DIM];
__device__ float g_P2[C_DIM * C_DIM];
__device__ float g_P3[C_DIM * C_DIM];
__device__ float g_trace;
__device__ float g_rTr;

// ---------------- mean per channel + zero scratch ----------------
__global__ void mean_kernel(const float* __restrict__ X) {
    int c = blockIdx.x;
    float s = 0.f;
    // 16384 float4 per channel
    for (int idx = threadIdx.x; idx < (M_TOT / 4); idx += 256) {
        int n = idx >> 8;            // 256 float4 per (n, c) row of 1024
        int h4 = idx & 255;
        const float4 v = *(const float4*)&X[(((size_t)(n * C_DIM + c)) << 10) + (size_t)h4 * 4];
        s += (v.x + v.y) + (v.z + v.w);
    }
    __shared__ float red[256];
    red[threadIdx.x] = s;
    __syncthreads();
    for (int off = 128; off > 0; off >>= 1) {
        if (threadIdx.x < off) red[threadIdx.x] += red[threadIdx.x + off];
        __syncthreads();
    }
    if (threadIdx.x == 0) g_mean[c] = red[0] * (1.0f / (float)M_TOT);
    // zero Gram row c (must happen every graph replay, before gram_kernel)
    for (int j = threadIdx.x; j < C_DIM; j += 256) g_Gram[c * C_DIM + j] = 0.f;
    if (c == 0 && threadIdx.x == 0) g_trace = 0.f;
}

// ---------------- Gram = x x^T (upper tiles only), split over n ----------------
// grid (36, 16), block 256. blockIdx.x -> (bi,bj) with bi<=bj ; blockIdx.y -> 4 n's
__global__ void gram_kernel(const float* __restrict__ X) {
    int t = blockIdx.x;
    int bi = 0;
    while (t >= 8 - bi) { t -= 8 - bi; bi++; }
    int bj = bi + t;

    __shared__ float As[32][68];
    __shared__ float Bs[32][68];

    const int tid = threadIdx.x;
    const int tx = tid & 15, ty = tid >> 4;
    float acc[4][4] = {};

    const int n0 = blockIdx.y * (N_DIM / 16);
    for (int n = n0; n < n0 + (N_DIM / 16); n++) {
        const float* A = X + (((size_t)(n * C_DIM + bi * 64)) << 10);
        const float* B = X + (((size_t)(n * C_DIM + bj * 64)) << 10);
        for (int k0 = 0; k0 < HW_DIM; k0 += 32) {
#pragma unroll
            for (int r = 0; r < 2; r++) {
                int lid = tid + r * 256;          // 0..511
                int k4 = lid & 7, row = lid >> 3; // row 0..63
                float4 v = *(const float4*)&A[(size_t)row * HW_DIM + k0 + k4 * 4];
                As[k4 * 4 + 0][row] = v.x; As[k4 * 4 + 1][row] = v.y;
                As[k4 * 4 + 2][row] = v.z; As[k4 * 4 + 3][row] = v.w;
                float4 u = *(const float4*)&B[(size_t)row * HW_DIM + k0 + k4 * 4];
                Bs[k4 * 4 + 0][row] = u.x; Bs[k4 * 4 + 1][row] = u.y;
                Bs[k4 * 4 + 2][row] = u.z; Bs[k4 * 4 + 3][row] = u.w;
            }
            __syncthreads();
#pragma unroll
            for (int kk = 0; kk < 32; kk++) {
                float4 a = *(const float4*)&As[kk][ty * 4];
                float4 b = *(const float4*)&Bs[kk][tx * 4];
                float av[4] = {a.x, a.y, a.z, a.w};
                float bv[4] = {b.x, b.y, b.z, b.w};
#pragma unroll
                for (int i = 0; i < 4; i++)
#pragma unroll
                    for (int j = 0; j < 4; j++)
                        acc[i][j] = fmaf(av[i], bv[j], acc[i][j]);
            }
            __syncthreads();
        }
    }
    const int ibase = bi * 64 + ty * 4;
    const int jbase = bj * 64 + tx * 4;
#pragma unroll
    for (int i = 0; i < 4; i++)
#pragma unroll
        for (int j = 0; j < 4; j++)
            atomicAdd(&g_Gram[(ibase + i) * C_DIM + jbase + j], acc[i][j]);
}

// ---------------- Sigma = Gram/m - mu mu^T + eps I ; trace ; P = I ----------------
__global__ void finalize_sigma() {
    int i = blockIdx.x;
    float mi = g_mean[i];
    for (int j = threadIdx.x; j < C_DIM; j += 256) {
        float raw = ((i >> 6) <= (j >> 6)) ? g_Gram[i * C_DIM + j] : g_Gram[j * C_DIM + i];
        float s = raw * (1.0f / (float)M_TOT) - mi * g_mean[j];
        if (i == j) { s += EPS_V; atomicAdd(&g_trace, s); }
        g_S[i * C_DIM + j] = s;
        g_Pa[i * C_DIM + j] = (i == j) ? 1.f : 0.f;
    }
}

// ---------------- Sigma_N = Sigma / trace ----------------
__global__ void scale_sigma() {
    float r = 1.0f / g_trace;
    int idx = blockIdx.x * 256 + threadIdx.x;
    g_S[idx] *= r;
    if (idx == 0) g_rTr = r;
}

// ---------------- C = alpha*(A@B) + beta*D  (512x512x512) ----------------
// grid (8,8), block 256
__global__ void gemm512(float* __restrict__ Cm, const float* __restrict__ A,
                        const float* __restrict__ B, const float* __restrict__ D,
                        float alpha, float beta) {
    __shared__ float As[32][68];
    __shared__ float Bs[32][68];
    const int bi = blockIdx.y, bj = blockIdx.x;
    const int tid = threadIdx.x;
    const int tx = tid & 15, ty = tid >> 4;
    float acc[4][4] = {};

    for (int k0 = 0; k0 < C_DIM; k0 += 32) {
#pragma unroll
        for (int r = 0; r < 2; r++) {
            int lid = tid + r * 256;
            int k4 = lid & 7, row = lid >> 3;
            float4 v = *(const float4*)&A[(size_t)(bi * 64 + row) * C_DIM + k0 + k4 * 4];
            As[k4 * 4 + 0][row] = v.x; As[k4 * 4 + 1][row] = v.y;
            As[k4 * 4 + 2][row] = v.z; As[k4 * 4 + 3][row] = v.w;
        }
#pragma unroll
        for (int r = 0; r < 2; r++) {
            int lid = tid + r * 256;
            int j4 = lid & 15, kk = (lid >> 4); // kk 0..31
            float4 v = *(const float4*)&B[(size_t)(k0 + kk) * C_DIM + bj * 64 + j4 * 4];
            *(float4*)&Bs[kk][j4 * 4] = v;
        }
        __syncthreads();
#pragma unroll
        for (int kk = 0; kk < 32; kk++) {
            float4 a = *(const float4*)&As[kk][ty * 4];
            float4 b = *(const float4*)&Bs[kk][tx * 4];
            float av[4] = {a.x, a.y, a.z, a.w};
            float bv[4] = {b.x, b.y, b.z, b.w};
#pragma unroll
            for (int i = 0; i < 4; i++)
#pragma unroll
                for (int j = 0; j < 4; j++)
                    acc[i][j] = fmaf(av[i], bv[j], acc[i][j]);
        }
        __syncthreads();
    }
#pragma unroll
    for (int i = 0; i < 4; i++)
#pragma unroll
        for (int j = 0; j < 4; j++) {
            size_t idx = (size_t)(bi * 64 + ty * 4 + i) * C_DIM + bj * 64 + tx * 4 + j;
            float v = alpha * acc[i][j];
            if (D) v = fmaf(beta, D[idx], v);
            Cm[idx] = v;
        }
}

// ---------------- bias[c] = sqrt(rTr) * dot(P[c,:], mean) ----------------
__global__ void bias_kernel(const float* __restrict__ P) {
    int c = blockIdx.x * 256 + threadIdx.x;
    float s = 0.f;
    for (int j = 0; j < C_DIM; j++) s = fmaf(P[c * C_DIM + j], g_mean[j], s);
    g_bias[c] = sqrtf(g_rTr) * s;
}

// ---------------- Out[n] = sqrt(rTr)*(P @ X_n) - bias ----------------
// grid (16, 8, 64), block 256
__global__ void out_kernel(const float* __restrict__ X, const float* __restrict__ P,
                           float* __restrict__ Out) {
    __shared__ float As[32][68];
    __shared__ float Bs[32][68];
    const int n = blockIdx.z, bs = blockIdx.x, bc = blockIdx.y;
    const int tid = threadIdx.x;
    const int tx = tid & 15, ty = tid >> 4;
    float acc[4][4] = {};
    const float* B = X + (((size_t)n * C_DIM) << 10);

    for (int k0 = 0; k0 < C_DIM; k0 += 32) {
#pragma unroll
        for (int r = 0; r < 2; r++) {
            int lid = tid + r * 256;
            int k4 = lid & 7, row = lid >> 3;
            float4 v = *(const float4*)&P[(size_t)(bc * 64 + row) * C_DIM + k0 + k4 * 4];
            As[k4 * 4 + 0][row] = v.x; As[k4 * 4 + 1][row] = v.y;
            As[k4 * 4 + 2][row] = v.z; As[k4 * 4 + 3][row] = v.w;
        }
#pragma unroll
        for (int r = 0; r < 2; r++) {
            int lid = tid + r * 256;
            int j4 = lid & 15, kk = lid >> 4;
            float4 v = *(const float4*)&B[(size_t)(k0 + kk) * HW_DIM + bs * 64 + j4 * 4];
            *(float4*)&Bs[kk][j4 * 4] = v;
        }
        __syncthreads();
#pragma unroll
        for (int kk = 0; kk < 32; kk++) {
            float4 a = *(const float4*)&As[kk][ty * 4];
            float4 b = *(const float4*)&Bs[kk][tx * 4];
            float av[4] = {a.x, a.y, a.z, a.w};
            float bv[4] = {b.x, b.y, b.z, b.w};
#pragma unroll
            for (int i = 0; i < 4; i++)
#pragma unroll
                for (int j = 0; j < 4; j++)
                    acc[i][j] = fmaf(av[i], bv[j], acc[i][j]);
        }
        __syncthreads();
    }
    const float sc = sqrtf(g_rTr);
#pragma unroll
    for (int i = 0; i < 4; i++) {
        int c = bc * 64 + ty * 4 + i;
        float bv = g_bias[c];
#pragma unroll
        for (int j = 0; j < 4; j++) {
            size_t idx = (((size_t)(n * C_DIM + c)) << 10) + bs * 64 + tx * 4 + j;
            Out[idx] = sc * acc[i][j] - bv;
        }
    }
}

// ---------------- launch ----------------
extern "C" void kernel_launch(void* const* d_in, const int* in_sizes, int n_in,
                              void* d_out, int out_size) {
    const float* X = (const float*)d_in[0];
    float* Out = (float*)d_out;

    float *Pa, *Pb, *P2, *P3, *S;
    cudaGetSymbolAddress((void**)&Pa, g_Pa);
    cudaGetSymbolAddress((void**)&Pb, g_Pb);
    cudaGetSymbolAddress((void**)&P2, g_P2);
    cudaGetSymbolAddress((void**)&P3, g_P3);
    cudaGetSymbolAddress((void**)&S,  g_S);

    mean_kernel<<<C_DIM, 256>>>(X);
    gram_kernel<<<dim3(36, 16), 256>>>(X);
    finalize_sigma<<<C_DIM, 256>>>();
    scale_sigma<<<(C_DIM * C_DIM) / 256, 256>>>();

    float* cur = Pa;
    float* nxt = Pb;
    for (int it = 0; it < T_ITERS; it++) {
        gemm512<<<dim3(8, 8), 256>>>(P2, cur, cur, (const float*)nullptr, 1.f, 0.f);
        gemm512<<<dim3(8, 8), 256>>>(P3, P2, cur, (const float*)nullptr, 1.f, 0.f);
        gemm512<<<dim3(8, 8), 256>>>(nxt, P3, S, cur, -0.5f, 1.5f);
        float* tmp = cur; cur = nxt; nxt = tmp;
    }

    bias_kernel<<<2, 256>>>(cur);
    out_kernel<<<dim3(16, 8, 64), 256>>>(X, cur, Out);
}